// round 6
// baseline (speedup 1.0000x reference)
#include <cuda_runtime.h>
#include <math.h>

#define B_    16
#define L_    128
#define V_    32000
#define G4_   4096
#define K_    1024
#define T_    127
#define M_    2032
#define MPAD_ 2048
#define LDSK  36

__device__ float g_X[MPAD_ * K_];
__device__ float g_xall[(size_t)MPAD_ * G4_];
__device__ float g_Hs[MPAD_ * K_];
__device__ float g_h[B_ * K_];
__device__ unsigned g_bar;

// ---------------------------------------------------------------- prep
__global__ void __launch_bounds__(256) prep_kernel(
    const float* __restrict__ latent, const float* __restrict__ emb,
    const int* __restrict__ target, float* __restrict__ out) {
  long i = (long)blockIdx.x * blockDim.x + threadIdx.x;
  if (i == 0) g_bar = 0u;
  const long Z = (long)B_ * (V_ / 4) * 1;           // 128000: out l=0 rows
  const long X = (long)M_ * 256;                    // 520192
  if (i < Z) {
    long b = i / 8000, v4 = i % 8000;
    ((float4*)out)[b * ((long)L_ * V_ / 4) + v4] = make_float4(0.f, 0.f, 0.f, 0.f);
  } else if (i < Z + X) {
    long j = i - Z;
    int m = (int)(j / 256), c4 = (int)(j % 256);
    int s = m >> 4, b = m & 15;
    float4 v;
    if (c4 < 128) {
      int tok = target[b * L_ + s];
      v = ((const float4*)emb)[(size_t)tok * 128 + c4];
    } else {
      v = ((const float4*)latent)[b * 128 + (c4 - 128)];
    }
    ((float4*)g_X)[(size_t)m * 256 + c4] = v;
  } else {
    long k = i - Z - X;
    if (k < 4096) ((float4*)g_h)[k] = make_float4(0.f, 0.f, 0.f, 0.f);
  }
}

// ---------------------------------------------------------------- tf32 split GEMM
__device__ __forceinline__ void tf32s(float x, unsigned& h, unsigned& l) {
  asm("cvt.rna.tf32.f32 %0, %1;" : "=r"(h) : "f"(x));
  float r = x - __uint_as_float(h);
  asm("cvt.rna.tf32.f32 %0, %1;" : "=r"(l) : "f"(r));
}
__device__ __forceinline__ void spl4(unsigned* ph, unsigned* pl, float4 v) {
  tf32s(v.x, ph[0], pl[0]); tf32s(v.y, ph[1], pl[1]);
  tf32s(v.z, ph[2], pl[2]); tf32s(v.w, ph[3], pl[3]);
}
__device__ __forceinline__ void mma8(float* c, const unsigned* a, const unsigned* b) {
  asm volatile(
    "mma.sync.aligned.m16n8k8.row.col.f32.tf32.tf32.f32 "
    "{%0,%1,%2,%3}, {%4,%5,%6,%7}, {%8,%9}, {%0,%1,%2,%3};\n"
    : "+f"(c[0]), "+f"(c[1]), "+f"(c[2]), "+f"(c[3])
    : "r"(a[0]), "r"(a[1]), "r"(a[2]), "r"(a[3]), "r"(b[0]), "r"(b[1]));
}

template <int EPI>
__global__ void __launch_bounds__(256) gemm_kernel(
    const float* __restrict__ Bm, const float* __restrict__ bias0,
    const float* __restrict__ bias1, float* __restrict__ Cout) {
  extern __shared__ unsigned sm[];
  unsigned* ah = sm;
  unsigned* al = sm + 128 * LDSK;
  unsigned* bh = sm + 2 * 128 * LDSK;
  unsigned* bl = sm + 3 * 128 * LDSK;
  const float* A = (EPI == 0) ? g_X : g_Hs;
  const int tid = threadIdx.x, lane = tid & 31, warp = tid >> 5;
  const int wm = warp >> 1, wn = warp & 1, grp = lane >> 2, tig = lane & 3;
  const int m0 = blockIdx.x * 128, n0 = blockIdx.y * 128;
  const int lr = tid >> 3, lc = (tid & 7) * 4;

  float acc[2][8][4];
#pragma unroll
  for (int a = 0; a < 2; a++)
#pragma unroll
    for (int b = 0; b < 8; b++)
#pragma unroll
      for (int c = 0; c < 4; c++) acc[a][b][c] = 0.f;

  float4 ra[4], rb[4];
#pragma unroll
  for (int i = 0; i < 4; i++) {
    ra[i] = *(const float4*)(A + (size_t)(m0 + lr + i * 32) * K_ + lc);
    rb[i] = *(const float4*)(Bm + (size_t)(n0 + lr + i * 32) * K_ + lc);
  }

  for (int k0 = 0; k0 < K_; k0 += 32) {
#pragma unroll
    for (int i = 0; i < 4; i++) {
      int r = lr + i * 32;
      spl4(ah + r * LDSK + lc, al + r * LDSK + lc, ra[i]);
      spl4(bh + r * LDSK + lc, bl + r * LDSK + lc, rb[i]);
    }
    __syncthreads();
    if (k0 + 32 < K_) {
#pragma unroll
      for (int i = 0; i < 4; i++) {
        ra[i] = *(const float4*)(A + (size_t)(m0 + lr + i * 32) * K_ + k0 + 32 + lc);
        rb[i] = *(const float4*)(Bm + (size_t)(n0 + lr + i * 32) * K_ + k0 + 32 + lc);
      }
    }
#pragma unroll
    for (int kk = 0; kk < 4; kk++) {
      const int kb = kk * 8;
      unsigned aH[2][4], aL[2][4];
#pragma unroll
      for (int mi = 0; mi < 2; mi++) {
        int r0 = (wm * 32 + mi * 16 + grp) * LDSK + kb + tig;
        aH[mi][0] = ah[r0];            aL[mi][0] = al[r0];
        aH[mi][1] = ah[r0 + 8 * LDSK]; aL[mi][1] = al[r0 + 8 * LDSK];
        aH[mi][2] = ah[r0 + 4];        aL[mi][2] = al[r0 + 4];
        aH[mi][3] = ah[r0 + 8 * LDSK + 4]; aL[mi][3] = al[r0 + 8 * LDSK + 4];
      }
#pragma unroll
      for (int ni = 0; ni < 8; ni++) {
        int rn = (wn * 64 + ni * 8 + grp) * LDSK + kb + tig;
        unsigned bhv[2] = {bh[rn], bh[rn + 4]};
        unsigned blv[2] = {bl[rn], bl[rn + 4]};
#pragma unroll
        for (int mi = 0; mi < 2; mi++) {
          mma8(acc[mi][ni], aH[mi], bhv);
          mma8(acc[mi][ni], aH[mi], blv);
          mma8(acc[mi][ni], aL[mi], bhv);
        }
      }
    }
    __syncthreads();
  }

#pragma unroll
  for (int mi = 0; mi < 2; mi++)
#pragma unroll
    for (int ni = 0; ni < 8; ni++) {
      int mr = m0 + wm * 32 + mi * 16 + grp;
      int nc = n0 + wn * 64 + ni * 8 + tig * 2;
      float* cp = acc[mi][ni];
      float b0 = bias0[nc] + ((EPI == 0) ? bias1[nc] : 0.f);
      float b1 = bias0[nc + 1] + ((EPI == 0) ? bias1[nc + 1] : 0.f);
      if (EPI == 0) {
        if (mr < M_) {
          g_xall[(size_t)mr * G4_ + nc] = cp[0] + b0;
          g_xall[(size_t)mr * G4_ + nc + 1] = cp[1] + b1;
        }
        if (mr + 8 < M_) {
          g_xall[(size_t)(mr + 8) * G4_ + nc] = cp[2] + b0;
          g_xall[(size_t)(mr + 8) * G4_ + nc + 1] = cp[3] + b1;
        }
      } else {
        if (mr < M_) {
          size_t o = ((size_t)(mr & 15) * L_ + (mr >> 4) + 1) * V_ + nc;
          Cout[o] = cp[0] + b0; Cout[o + 1] = cp[1] + b1;
        }
        if (mr + 8 < M_) {
          int m2 = mr + 8;
          size_t o = ((size_t)(m2 & 15) * L_ + (m2 >> 4) + 1) * V_ + nc;
          Cout[o] = cp[2] + b0; Cout[o + 1] = cp[3] + b1;
        }
      }
    }
}

// ---------------------------------------------------------------- recurrence
__device__ __forceinline__ float sigf(float x) { return 1.f / (1.f + __expf(-x)); }

__global__ void __launch_bounds__(256) recur_kernel(const float* __restrict__ Whh) {
  extern __shared__ float hs[];   // 16 x 1024 floats
  const int tid = threadIdx.x, lane = tid & 31, warp = tid >> 5;
  const int u = blockIdx.x * 8 + warp;   // hidden unit owned by this warp
  float c = 0.f;
  unsigned tgt = 0;

  for (int s = 0; s < T_; s++) {
    for (int j = tid; j < 4096; j += 256)
      ((float4*)hs)[j] = __ldcg((const float4*)g_h + j);
    __syncthreads();

    float acc[4][16];
#pragma unroll
    for (int g = 0; g < 4; g++)
#pragma unroll
      for (int b = 0; b < 16; b++) acc[g][b] = 0.f;

#pragma unroll
    for (int i = 0; i < 8; i++) {
      const int k = lane * 4 + i * 128;
      float4 w0 = *(const float4*)(Whh + ((size_t)(0 * K_ + u)) * K_ + k);
      float4 w1 = *(const float4*)(Whh + ((size_t)(1 * K_ + u)) * K_ + k);
      float4 w2 = *(const float4*)(Whh + ((size_t)(2 * K_ + u)) * K_ + k);
      float4 w3 = *(const float4*)(Whh + ((size_t)(3 * K_ + u)) * K_ + k);
#pragma unroll
      for (int b = 0; b < 16; b++) {
        float4 h4 = *(const float4*)(hs + b * K_ + k);
        acc[0][b] += w0.x * h4.x; acc[0][b] += w0.y * h4.y;
        acc[0][b] += w0.z * h4.z; acc[0][b] += w0.w * h4.w;
        acc[1][b] += w1.x * h4.x; acc[1][b] += w1.y * h4.y;
        acc[1][b] += w1.z * h4.z; acc[1][b] += w1.w * h4.w;
        acc[2][b] += w2.x * h4.x; acc[2][b] += w2.y * h4.y;
        acc[2][b] += w2.z * h4.z; acc[2][b] += w2.w * h4.w;
        acc[3][b] += w3.x * h4.x; acc[3][b] += w3.y * h4.y;
        acc[3][b] += w3.z * h4.z; acc[3][b] += w3.w * h4.w;
      }
    }

#pragma unroll
    for (int g = 0; g < 4; g++)
#pragma unroll
      for (int b = 0; b < 16; b++)
#pragma unroll
        for (int off = 16; off; off >>= 1)
          acc[g][b] += __shfl_xor_sync(0xffffffffu, acc[g][b], off);

    if (lane < 16) {
      float gi = 0.f, gf = 0.f, gg = 0.f, go = 0.f;
#pragma unroll
      for (int b = 0; b < 16; b++)
        if (b == lane) { gi = acc[0][b]; gf = acc[1][b]; gg = acc[2][b]; go = acc[3][b]; }
      size_t xr = ((size_t)s * 16 + lane) * G4_ + u;
      gi += g_xall[xr];
      gf += g_xall[xr + 1024];
      gg += g_xall[xr + 2048];
      go += g_xall[xr + 3072];
      c = sigf(gf) * c + sigf(gi) * tanhf(gg);
      float h = sigf(go) * tanhf(c);
      g_h[lane * K_ + u] = h;
      g_Hs[((size_t)s * 16 + lane) * K_ + u] = h;
    }

    __threadfence();
    __syncthreads();
    tgt += gridDim.x;
    if (tid == 0) {
      atomicAdd(&g_bar, 1u);
      while (*(volatile unsigned*)&g_bar < tgt) {}
    }
    __syncthreads();
  }
}

// ---------------------------------------------------------------- launch
extern "C" void kernel_launch(void* const* d_in, const int* in_sizes, int n_in,
                              void* d_out, int out_size) {
  const float* latent = (const float*)d_in[0];
  const float* emb    = (const float*)d_in[1];
  const float* W_ih   = (const float*)d_in[2];
  const float* W_hh   = (const float*)d_in[3];
  const float* b_ih   = (const float*)d_in[4];
  const float* b_hh   = (const float*)d_in[5];
  const float* fc_w   = (const float*)d_in[6];
  const float* fc_b   = (const float*)d_in[7];
  const int*   target = (const int*)d_in[8];
  float* out = (float*)d_out;

  cudaFuncSetAttribute(gemm_kernel<0>, cudaFuncAttributeMaxDynamicSharedMemorySize, 4 * 128 * LDSK * 4);
  cudaFuncSetAttribute(gemm_kernel<1>, cudaFuncAttributeMaxDynamicSharedMemorySize, 4 * 128 * LDSK * 4);
  cudaFuncSetAttribute(recur_kernel, cudaFuncAttributeMaxDynamicSharedMemorySize, 16 * K_ * 4);

  prep_kernel<<<2548, 256>>>(latent, emb, target, out);
  gemm_kernel<0><<<dim3(16, 32), 256, 4 * 128 * LDSK * 4>>>(W_ih, b_ih, b_hh, nullptr);
  recur_kernel<<<128, 256, 16 * K_ * 4>>>(W_hh);
  gemm_kernel<1><<<dim3(16, 250), 256, 4 * 128 * LDSK * 4>>>(fc_w, fc_b, nullptr, out);
}

// round 10
// speedup vs baseline: 2.1267x; 2.1267x over previous
#include <cuda_runtime.h>
#include <cuda_bf16.h>
#include <math.h>

#define B_    16
#define L_    128
#define V_    32000
#define G4_   4096
#define K_    1024
#define T_    127
#define M_    2032
#define MPAD_ 2048
#define PD    20      // smem row stride in u32 (16 pairs + pad), conflict-free frag loads

__device__ float g_X[MPAD_ * K_];
__device__ float g_xall[(size_t)MPAD_ * G4_];
__device__ float g_Hs[MPAD_ * K_];
__device__ float g_h[B_ * K_];
__device__ unsigned g_bar;

// ---------------------------------------------------------------- prep
__global__ void __launch_bounds__(256) prep_kernel(
    const float* __restrict__ latent, const float* __restrict__ emb,
    const int* __restrict__ target, float* __restrict__ out) {
  long i = (long)blockIdx.x * blockDim.x + threadIdx.x;
  if (i == 0) g_bar = 0u;
  const long Z = (long)B_ * (V_ / 4);               // 128000: out l=0 rows
  const long X = (long)M_ * 256;                    // 520192
  if (i < Z) {
    long b = i / 8000, v4 = i % 8000;
    ((float4*)out)[b * ((long)L_ * V_ / 4) + v4] = make_float4(0.f, 0.f, 0.f, 0.f);
  } else if (i < Z + X) {
    long j = i - Z;
    int m = (int)(j / 256), c4 = (int)(j % 256);
    int s = m >> 4, b = m & 15;
    float4 v;
    if (c4 < 128) {
      int tok = target[b * L_ + s];
      v = ((const float4*)emb)[(size_t)tok * 128 + c4];
    } else {
      v = ((const float4*)latent)[b * 128 + (c4 - 128)];
    }
    ((float4*)g_X)[(size_t)m * 256 + c4] = v;
  } else {
    long k = i - Z - X;
    if (k < 4096) ((float4*)g_h)[k] = make_float4(0.f, 0.f, 0.f, 0.f);
  }
}

// ---------------------------------------------------------------- bf16-split GEMM
// x = hi + lo, hi = bf16(x), lo = bf16(x - hi). 3 MMAs: hi*hi + hi*lo + lo*hi.
__device__ __forceinline__ unsigned pack2(__nv_bfloat16 a, __nv_bfloat16 b) {
  __nv_bfloat162 t; t.x = a; t.y = b;
  return *(unsigned*)&t;
}
__device__ __forceinline__ void bsplit2(float x0, float x1, unsigned& h, unsigned& l) {
  __nv_bfloat16 h0 = __float2bfloat16(x0);
  __nv_bfloat16 h1 = __float2bfloat16(x1);
  float r0 = x0 - __bfloat162float(h0);
  float r1 = x1 - __bfloat162float(h1);
  h = pack2(h0, h1);
  l = pack2(__float2bfloat16(r0), __float2bfloat16(r1));
}
__device__ __forceinline__ void mma16(float* c, const unsigned* a, const unsigned* b) {
  asm volatile(
    "mma.sync.aligned.m16n8k16.row.col.f32.bf16.bf16.f32 "
    "{%0,%1,%2,%3}, {%4,%5,%6,%7}, {%8,%9}, {%0,%1,%2,%3};\n"
    : "+f"(c[0]), "+f"(c[1]), "+f"(c[2]), "+f"(c[3])
    : "r"(a[0]), "r"(a[1]), "r"(a[2]), "r"(a[3]), "r"(b[0]), "r"(b[1]));
}

template <int EPI>
__global__ void __launch_bounds__(256) gemm_kernel(
    const float* __restrict__ Bm, const float* __restrict__ bias0,
    const float* __restrict__ bias1, float* __restrict__ Cout) {
  __shared__ unsigned ah[128 * PD];
  __shared__ unsigned al[128 * PD];
  __shared__ unsigned bh[128 * PD];
  __shared__ unsigned bl[128 * PD];
  const float* A = (EPI == 0) ? g_X : g_Hs;
  const int tid = threadIdx.x, lane = tid & 31, warp = tid >> 5;
  const int wm = warp >> 1, wn = warp & 1, grp = lane >> 2, tig = lane & 3;
  const int m0 = blockIdx.x * 128, n0 = blockIdx.y * 128;
  const int lr = tid >> 3, lc = (tid & 7) * 4;   // load: 4 floats -> 2 pair-u32
  const int pc = (tid & 7) * 2;                  // pair column for smem write

  float acc[2][8][4];
#pragma unroll
  for (int a = 0; a < 2; a++)
#pragma unroll
    for (int b = 0; b < 8; b++)
#pragma unroll
      for (int c = 0; c < 4; c++) acc[a][b][c] = 0.f;

  float4 ra[4], rb[4];
#pragma unroll
  for (int i = 0; i < 4; i++) {
    ra[i] = *(const float4*)(A + (size_t)(m0 + lr + i * 32) * K_ + lc);
    rb[i] = *(const float4*)(Bm + (size_t)(n0 + lr + i * 32) * K_ + lc);
  }

  for (int k0 = 0; k0 < K_; k0 += 32) {
#pragma unroll
    for (int i = 0; i < 4; i++) {
      int r = lr + i * 32;
      unsigned h0, l0, h1, l1;
      bsplit2(ra[i].x, ra[i].y, h0, l0);
      bsplit2(ra[i].z, ra[i].w, h1, l1);
      ah[r * PD + pc] = h0; ah[r * PD + pc + 1] = h1;
      al[r * PD + pc] = l0; al[r * PD + pc + 1] = l1;
      bsplit2(rb[i].x, rb[i].y, h0, l0);
      bsplit2(rb[i].z, rb[i].w, h1, l1);
      bh[r * PD + pc] = h0; bh[r * PD + pc + 1] = h1;
      bl[r * PD + pc] = l0; bl[r * PD + pc + 1] = l1;
    }
    __syncthreads();
    if (k0 + 32 < K_) {
#pragma unroll
      for (int i = 0; i < 4; i++) {
        ra[i] = *(const float4*)(A + (size_t)(m0 + lr + i * 32) * K_ + k0 + 32 + lc);
        rb[i] = *(const float4*)(Bm + (size_t)(n0 + lr + i * 32) * K_ + k0 + 32 + lc);
      }
    }
#pragma unroll
    for (int kk = 0; kk < 2; kk++) {        // two k16 steps per BK=32
      const int pb = kk * 8;                // pair base
      unsigned aH[2][4], aL[2][4];
#pragma unroll
      for (int mi = 0; mi < 2; mi++) {
        int r0 = (wm * 32 + mi * 16 + grp) * PD + pb + tig;
        int r1 = r0 + 8 * PD;
        aH[mi][0] = ah[r0];     aL[mi][0] = al[r0];
        aH[mi][1] = ah[r1];     aL[mi][1] = al[r1];
        aH[mi][2] = ah[r0 + 4]; aL[mi][2] = al[r0 + 4];
        aH[mi][3] = ah[r1 + 4]; aL[mi][3] = al[r1 + 4];
      }
#pragma unroll
      for (int ni = 0; ni < 8; ni++) {
        int rn = (wn * 64 + ni * 8 + grp) * PD + pb + tig;
        unsigned bH[2] = {bh[rn], bh[rn + 4]};
        unsigned bL[2] = {bl[rn], bl[rn + 4]};
#pragma unroll
        for (int mi = 0; mi < 2; mi++) {
          mma16(acc[mi][ni], aH[mi], bH);
          mma16(acc[mi][ni], aH[mi], bL);
          mma16(acc[mi][ni], aL[mi], bH);
        }
      }
    }
    __syncthreads();
  }

#pragma unroll
  for (int mi = 0; mi < 2; mi++)
#pragma unroll
    for (int ni = 0; ni < 8; ni++) {
      int mr = m0 + wm * 32 + mi * 16 + grp;
      int nc = n0 + wn * 64 + ni * 8 + tig * 2;
      float* cp = acc[mi][ni];
      float b0 = bias0[nc] + ((EPI == 0) ? bias1[nc] : 0.f);
      float b1 = bias0[nc + 1] + ((EPI == 0) ? bias1[nc + 1] : 0.f);
      if (EPI == 0) {
        if (mr < M_) {
          g_xall[(size_t)mr * G4_ + nc] = cp[0] + b0;
          g_xall[(size_t)mr * G4_ + nc + 1] = cp[1] + b1;
        }
        if (mr + 8 < M_) {
          g_xall[(size_t)(mr + 8) * G4_ + nc] = cp[2] + b0;
          g_xall[(size_t)(mr + 8) * G4_ + nc + 1] = cp[3] + b1;
        }
      } else {
        if (mr < M_) {
          size_t o = ((size_t)(mr & 15) * L_ + (mr >> 4) + 1) * V_ + nc;
          Cout[o] = cp[0] + b0; Cout[o + 1] = cp[1] + b1;
        }
        if (mr + 8 < M_) {
          int m2 = mr + 8;
          size_t o = ((size_t)(m2 & 15) * L_ + (m2 >> 4) + 1) * V_ + nc;
          Cout[o] = cp[2] + b0; Cout[o + 1] = cp[3] + b1;
        }
      }
    }
}

// ---------------------------------------------------------------- recurrence
__device__ __forceinline__ float sigf(float x) { return 1.f / (1.f + __expf(-x)); }

__global__ void __launch_bounds__(256) recur_kernel(const float* __restrict__ Whh) {
  extern __shared__ float hs[];   // 16 x 1024 floats
  const int tid = threadIdx.x, lane = tid & 31, warp = tid >> 5;
  const int u = blockIdx.x * 8 + warp;   // hidden unit owned by this warp
  float c = 0.f;
  unsigned tgt = 0;

  for (int s = 0; s < T_; s++) {
    for (int j = tid; j < 4096; j += 256)
      ((float4*)hs)[j] = __ldcg((const float4*)g_h + j);
    __syncthreads();

    float acc[4][16];
#pragma unroll
    for (int g = 0; g < 4; g++)
#pragma unroll
      for (int b = 0; b < 16; b++) acc[g][b] = 0.f;

#pragma unroll
    for (int i = 0; i < 8; i++) {
      const int k = lane * 4 + i * 128;
      float4 w0 = *(const float4*)(Whh + ((size_t)(0 * K_ + u)) * K_ + k);
      float4 w1 = *(const float4*)(Whh + ((size_t)(1 * K_ + u)) * K_ + k);
      float4 w2 = *(const float4*)(Whh + ((size_t)(2 * K_ + u)) * K_ + k);
      float4 w3 = *(const float4*)(Whh + ((size_t)(3 * K_ + u)) * K_ + k);
#pragma unroll
      for (int b = 0; b < 16; b++) {
        float4 h4 = *(const float4*)(hs + b * K_ + k);
        acc[0][b] += w0.x * h4.x; acc[0][b] += w0.y * h4.y;
        acc[0][b] += w0.z * h4.z; acc[0][b] += w0.w * h4.w;
        acc[1][b] += w1.x * h4.x; acc[1][b] += w1.y * h4.y;
        acc[1][b] += w1.z * h4.z; acc[1][b] += w1.w * h4.w;
        acc[2][b] += w2.x * h4.x; acc[2][b] += w2.y * h4.y;
        acc[2][b] += w2.z * h4.z; acc[2][b] += w2.w * h4.w;
        acc[3][b] += w3.x * h4.x; acc[3][b] += w3.y * h4.y;
        acc[3][b] += w3.z * h4.z; acc[3][b] += w3.w * h4.w;
      }
    }

#pragma unroll
    for (int g = 0; g < 4; g++)
#pragma unroll
      for (int b = 0; b < 16; b++)
#pragma unroll
        for (int off = 16; off; off >>= 1)
          acc[g][b] += __shfl_xor_sync(0xffffffffu, acc[g][b], off);

    if (lane < 16) {
      float gi = 0.f, gf = 0.f, gg = 0.f, go = 0.f;
#pragma unroll
      for (int b = 0; b < 16; b++)
        if (b == lane) { gi = acc[0][b]; gf = acc[1][b]; gg = acc[2][b]; go = acc[3][b]; }
      size_t xr = ((size_t)s * 16 + lane) * G4_ + u;
      gi += g_xall[xr];
      gf += g_xall[xr + 1024];
      gg += g_xall[xr + 2048];
      go += g_xall[xr + 3072];
      c = sigf(gf) * c + sigf(gi) * tanhf(gg);
      float h = sigf(go) * tanhf(c);
      g_h[lane * K_ + u] = h;
      g_Hs[((size_t)s * 16 + lane) * K_ + u] = h;
    }

    __threadfence();
    __syncthreads();
    tgt += gridDim.x;
    if (tid == 0) {
      atomicAdd(&g_bar, 1u);
      while (*(volatile unsigned*)&g_bar < tgt) {}
    }
    __syncthreads();
  }
}

// ---------------------------------------------------------------- launch
extern "C" void kernel_launch(void* const* d_in, const int* in_sizes, int n_in,
                              void* d_out, int out_size) {
  const float* latent = (const float*)d_in[0];
  const float* emb    = (const float*)d_in[1];
  const float* W_ih   = (const float*)d_in[2];
  const float* W_hh   = (const float*)d_in[3];
  const float* b_ih   = (const float*)d_in[4];
  const float* b_hh   = (const float*)d_in[5];
  const float* fc_w   = (const float*)d_in[6];
  const float* fc_b   = (const float*)d_in[7];
  const int*   target = (const int*)d_in[8];
  float* out = (float*)d_out;

  cudaFuncSetAttribute(recur_kernel, cudaFuncAttributeMaxDynamicSharedMemorySize, 16 * K_ * 4);

  prep_kernel<<<2548, 256>>>(latent, emb, target, out);
  gemm_kernel<0><<<dim3(16, 32), 256>>>(W_ih, b_ih, b_hh, nullptr);
  recur_kernel<<<128, 256, 16 * K_ * 4>>>(W_hh);
  gemm_kernel<1><<<dim3(16, 250), 256>>>(fc_w, fc_b, nullptr, out);
}

// round 12
// speedup vs baseline: 2.1910x; 1.0302x over previous
#include <cuda_runtime.h>
#include <cuda_bf16.h>
#include <math.h>

#define B_    16
#define L_    128
#define V_    32000
#define G4_   4096
#define K_    1024
#define KP_   512     // u32 bf16-pairs per row
#define T_    127
#define M_    2032
#define MPAD_ 2048
#define PD    20      // smem row stride in u32 (16 data + 4 pad), 16B aligned
#define NSLAB 32      // K_/32

__device__ float g_X[MPAD_ * K_];
__device__ float g_xall[(size_t)MPAD_ * G4_];
__device__ float g_Hs[MPAD_ * K_];
__device__ float g_h[B_ * K_];
__device__ unsigned g_bar;
// bf16 hi/lo split matrices (u32 = packed bf16x2 along K)
__device__ unsigned g_AH[MPAD_ * KP_], g_AL[MPAD_ * KP_];           // X or Hs
__device__ unsigned g_WH[G4_ * KP_],  g_WL[G4_ * KP_];              // W_ih
__device__ unsigned g_FH[(size_t)V_ * KP_], g_FL[(size_t)V_ * KP_]; // fc_w

// ---------------------------------------------------------------- prep
__global__ void __launch_bounds__(256) prep_kernel(
    const float* __restrict__ latent, const float* __restrict__ emb,
    const int* __restrict__ target, float* __restrict__ out) {
  long i = (long)blockIdx.x * blockDim.x + threadIdx.x;
  if (i == 0) g_bar = 0u;
  const long Z = (long)B_ * (V_ / 4);               // 128000: out l=0 rows
  const long X = (long)M_ * 256;                    // 520192
  if (i < Z) {
    long b = i / 8000, v4 = i % 8000;
    ((float4*)out)[b * ((long)L_ * V_ / 4) + v4] = make_float4(0.f, 0.f, 0.f, 0.f);
  } else if (i < Z + X) {
    long j = i - Z;
    int m = (int)(j / 256), c4 = (int)(j % 256);
    int s = m >> 4, b = m & 15;
    float4 v;
    if (c4 < 128) {
      int tok = target[b * L_ + s];
      v = ((const float4*)emb)[(size_t)tok * 128 + c4];
    } else {
      v = ((const float4*)latent)[b * 128 + (c4 - 128)];
    }
    ((float4*)g_X)[(size_t)m * 256 + c4] = v;
  } else {
    long k = i - Z - X;
    if (k < 4096) ((float4*)g_h)[k] = make_float4(0.f, 0.f, 0.f, 0.f);
  }
}

// ---------------------------------------------------------------- bf16 split
__device__ __forceinline__ unsigned pack2(__nv_bfloat16 a, __nv_bfloat16 b) {
  __nv_bfloat162 t; t.x = a; t.y = b;
  return *(unsigned*)&t;
}
__device__ __forceinline__ void bsplit2(float x0, float x1, unsigned& h, unsigned& l) {
  __nv_bfloat16 h0 = __float2bfloat16(x0);
  __nv_bfloat16 h1 = __float2bfloat16(x1);
  float r0 = x0 - __bfloat162float(h0);
  float r1 = x1 - __bfloat162float(h1);
  h = pack2(h0, h1);
  l = pack2(__float2bfloat16(r0), __float2bfloat16(r1));
}

__global__ void __launch_bounds__(256) split_kernel(
    const float* __restrict__ src, unsigned* __restrict__ hi,
    unsigned* __restrict__ lo, long npairs) {
  long i = (long)blockIdx.x * blockDim.x + threadIdx.x;
  if (i < npairs) {
    float2 v = ((const float2*)src)[i];
    unsigned h, l;
    bsplit2(v.x, v.y, h, l);
    hi[i] = h; lo[i] = l;
  }
}

// ---------------------------------------------------------------- GEMM (bf16x3 split, cp.async double-buffered)
__device__ __forceinline__ void mma16(float* c, const unsigned* a, const unsigned* b) {
  asm volatile(
    "mma.sync.aligned.m16n8k16.row.col.f32.bf16.bf16.f32 "
    "{%0,%1,%2,%3}, {%4,%5,%6,%7}, {%8,%9}, {%0,%1,%2,%3};\n"
    : "+f"(c[0]), "+f"(c[1]), "+f"(c[2]), "+f"(c[3])
    : "r"(a[0]), "r"(a[1]), "r"(a[2]), "r"(a[3]), "r"(b[0]), "r"(b[1]));
}
__device__ __forceinline__ void cpa16(unsigned saddr, const void* gptr) {
  asm volatile("cp.async.cg.shared.global [%0], [%1], 16;\n" :: "r"(saddr), "l"(gptr));
}

#define TILE_U32 (128 * PD)

template <int EPI>
__global__ void __launch_bounds__(256) gemm_kernel(
    const unsigned* __restrict__ AH, const unsigned* __restrict__ AL,
    const unsigned* __restrict__ BH, const unsigned* __restrict__ BL,
    const float* __restrict__ bias0, const float* __restrict__ bias1,
    float* __restrict__ Cout) {
  extern __shared__ unsigned smem[];   // [2 stages][4 tiles][128*PD]
  const int tid = threadIdx.x, lane = tid & 31, warp = tid >> 5;
  const int wm = warp >> 1, wn = warp & 1, grp = lane >> 2, tig = lane & 3;
  const int m0 = blockIdx.x * 128, n0 = blockIdx.y * 128;

  const unsigned sbase = (unsigned)__cvta_generic_to_shared(smem);
  const int row = tid >> 2, c4 = (tid & 3) * 4;       // copy coords: rows tid/4, chunk
  // each thread copies 2 rows per tile: row and row+64

  float acc[2][8][4];
#pragma unroll
  for (int a = 0; a < 2; a++)
#pragma unroll
    for (int b = 0; b < 8; b++)
#pragma unroll
      for (int c = 0; c < 4; c++) acc[a][b][c] = 0.f;

  const unsigned* gsrc[4] = {AH, AL, BH, BL};

  // issue async copies for one slab into stage st
  auto issue = [&](int st, int kp0) {
#pragma unroll
    for (int t = 0; t < 4; t++) {
      const unsigned* g = gsrc[t];
      int rbase = (t < 2) ? m0 : n0;
      unsigned sdst = sbase + ((st * 4 + t) * TILE_U32) * 4u;
#pragma unroll
      for (int j = 0; j < 2; j++) {
        int r = row + j * 64;
        cpa16(sdst + (r * PD + c4) * 4u,
              g + (size_t)(rbase + r) * KP_ + kp0 + c4);
      }
    }
    asm volatile("cp.async.commit_group;\n");
  };

  issue(0, 0);

  for (int s = 0; s < NSLAB; s++) {
    const int st = s & 1;
    if (s + 1 < NSLAB) {
      issue(st ^ 1, (s + 1) * 16);
      asm volatile("cp.async.wait_group 1;\n");
    } else {
      asm volatile("cp.async.wait_group 0;\n");
    }
    __syncthreads();

    const unsigned* ah = smem + (st * 4 + 0) * TILE_U32;
    const unsigned* al = smem + (st * 4 + 1) * TILE_U32;
    const unsigned* bh = smem + (st * 4 + 2) * TILE_U32;
    const unsigned* bl = smem + (st * 4 + 3) * TILE_U32;

#pragma unroll
    for (int kk = 0; kk < 2; kk++) {
      const int pb = kk * 8;
      unsigned aH[2][4], aL[2][4];
#pragma unroll
      for (int mi = 0; mi < 2; mi++) {
        int r0 = (wm * 32 + mi * 16 + grp) * PD + pb + tig;
        int r1 = r0 + 8 * PD;
        aH[mi][0] = ah[r0];     aL[mi][0] = al[r0];
        aH[mi][1] = ah[r1];     aL[mi][1] = al[r1];
        aH[mi][2] = ah[r0 + 4]; aL[mi][2] = al[r0 + 4];
        aH[mi][3] = ah[r1 + 4]; aL[mi][3] = al[r1 + 4];
      }
#pragma unroll
      for (int ni = 0; ni < 8; ni++) {
        int rn = (wn * 64 + ni * 8 + grp) * PD + pb + tig;
        unsigned bH[2] = {bh[rn], bh[rn + 4]};
        unsigned bL[2] = {bl[rn], bl[rn + 4]};
#pragma unroll
        for (int mi = 0; mi < 2; mi++) {
          mma16(acc[mi][ni], aH[mi], bH);
          mma16(acc[mi][ni], aH[mi], bL);
          mma16(acc[mi][ni], aL[mi], bH);
        }
      }
    }
    __syncthreads();
  }

#pragma unroll
  for (int mi = 0; mi < 2; mi++)
#pragma unroll
    for (int ni = 0; ni < 8; ni++) {
      int mr = m0 + wm * 32 + mi * 16 + grp;
      int nc = n0 + wn * 64 + ni * 8 + tig * 2;
      float* cp = acc[mi][ni];
      float b0 = bias0[nc] + ((EPI == 0) ? bias1[nc] : 0.f);
      float b1 = bias0[nc + 1] + ((EPI == 0) ? bias1[nc + 1] : 0.f);
      if (EPI == 0) {
        if (mr < M_) {
          g_xall[(size_t)mr * G4_ + nc] = cp[0] + b0;
          g_xall[(size_t)mr * G4_ + nc + 1] = cp[1] + b1;
        }
        if (mr + 8 < M_) {
          g_xall[(size_t)(mr + 8) * G4_ + nc] = cp[2] + b0;
          g_xall[(size_t)(mr + 8) * G4_ + nc + 1] = cp[3] + b1;
        }
      } else {
        if (mr < M_) {
          size_t o = ((size_t)(mr & 15) * L_ + (mr >> 4) + 1) * V_ + nc;
          Cout[o] = cp[0] + b0; Cout[o + 1] = cp[1] + b1;
        }
        if (mr + 8 < M_) {
          int m2 = mr + 8;
          size_t o = ((size_t)(m2 & 15) * L_ + (m2 >> 4) + 1) * V_ + nc;
          Cout[o] = cp[2] + b0; Cout[o + 1] = cp[3] + b1;
        }
      }
    }
}

// ---------------------------------------------------------------- recurrence
__device__ __forceinline__ float sigf(float x) { return 1.f / (1.f + __expf(-x)); }

__global__ void __launch_bounds__(256) recur_kernel(const float* __restrict__ Whh) {
  extern __shared__ float hs[];   // 16 x 1024 floats
  const int tid = threadIdx.x, lane = tid & 31, warp = tid >> 5;
  const int u = blockIdx.x * 8 + warp;   // hidden unit owned by this warp
  float c = 0.f;
  unsigned tgt = 0;

  for (int s = 0; s < T_; s++) {
    for (int j = tid; j < 4096; j += 256)
      ((float4*)hs)[j] = __ldcg((const float4*)g_h + j);
    __syncthreads();

    float acc[4][16];
#pragma unroll
    for (int g = 0; g < 4; g++)
#pragma unroll
      for (int b = 0; b < 16; b++) acc[g][b] = 0.f;

#pragma unroll
    for (int i = 0; i < 8; i++) {
      const int k = lane * 4 + i * 128;
      float4 w0 = *(const float4*)(Whh + ((size_t)(0 * K_ + u)) * K_ + k);
      float4 w1 = *(const float4*)(Whh + ((size_t)(1 * K_ + u)) * K_ + k);
      float4 w2 = *(const float4*)(Whh + ((size_t)(2 * K_ + u)) * K_ + k);
      float4 w3 = *(const float4*)(Whh + ((size_t)(3 * K_ + u)) * K_ + k);
#pragma unroll
      for (int b = 0; b < 16; b++) {
        float4 h4 = *(const float4*)(hs + b * K_ + k);
        acc[0][b] += w0.x * h4.x; acc[0][b] += w0.y * h4.y;
        acc[0][b] += w0.z * h4.z; acc[0][b] += w0.w * h4.w;
        acc[1][b] += w1.x * h4.x; acc[1][b] += w1.y * h4.y;
        acc[1][b] += w1.z * h4.z; acc[1][b] += w1.w * h4.w;
        acc[2][b] += w2.x * h4.x; acc[2][b] += w2.y * h4.y;
        acc[2][b] += w2.z * h4.z; acc[2][b] += w2.w * h4.w;
        acc[3][b] += w3.x * h4.x; acc[3][b] += w3.y * h4.y;
        acc[3][b] += w3.z * h4.z; acc[3][b] += w3.w * h4.w;
      }
    }

#pragma unroll
    for (int g = 0; g < 4; g++)
#pragma unroll
      for (int b = 0; b < 16; b++)
#pragma unroll
        for (int off = 16; off; off >>= 1)
          acc[g][b] += __shfl_xor_sync(0xffffffffu, acc[g][b], off);

    if (lane < 16) {
      float gi = 0.f, gf = 0.f, gg = 0.f, go = 0.f;
#pragma unroll
      for (int b = 0; b < 16; b++)
        if (b == lane) { gi = acc[0][b]; gf = acc[1][b]; gg = acc[2][b]; go = acc[3][b]; }
      size_t xr = ((size_t)s * 16 + lane) * G4_ + u;
      gi += g_xall[xr];
      gf += g_xall[xr + 1024];
      gg += g_xall[xr + 2048];
      go += g_xall[xr + 3072];
      c = sigf(gf) * c + sigf(gi) * tanhf(gg);
      float h = sigf(go) * tanhf(c);
      g_h[lane * K_ + u] = h;
      g_Hs[((size_t)s * 16 + lane) * K_ + u] = h;
    }

    __threadfence();
    __syncthreads();
    tgt += gridDim.x;
    if (tid == 0) {
      atomicAdd(&g_bar, 1u);
      while (*(volatile unsigned*)&g_bar < tgt) {}
    }
    __syncthreads();
  }
}

// ---------------------------------------------------------------- launch
extern "C" void kernel_launch(void* const* d_in, const int* in_sizes, int n_in,
                              void* d_out, int out_size) {
  const float* latent = (const float*)d_in[0];
  const float* emb    = (const float*)d_in[1];
  const float* W_ih   = (const float*)d_in[2];
  const float* W_hh   = (const float*)d_in[3];
  const float* b_ih   = (const float*)d_in[4];
  const float* b_hh   = (const float*)d_in[5];
  const float* fc_w   = (const float*)d_in[6];
  const float* fc_b   = (const float*)d_in[7];
  const int*   target = (const int*)d_in[8];
  float* out = (float*)d_out;

  // resolve device-global addresses
  unsigned *AH, *AL, *WH, *WL, *FH, *FL;
  float *Xp, *Hsp;
  cudaGetSymbolAddress((void**)&AH, g_AH);
  cudaGetSymbolAddress((void**)&AL, g_AL);
  cudaGetSymbolAddress((void**)&WH, g_WH);
  cudaGetSymbolAddress((void**)&WL, g_WL);
  cudaGetSymbolAddress((void**)&FH, g_FH);
  cudaGetSymbolAddress((void**)&FL, g_FL);
  cudaGetSymbolAddress((void**)&Xp, g_X);
  cudaGetSymbolAddress((void**)&Hsp, g_Hs);

  const int SM_GEMM = 2 * 4 * TILE_U32 * 4;   // 81920 B
  cudaFuncSetAttribute(gemm_kernel<0>, cudaFuncAttributeMaxDynamicSharedMemorySize, SM_GEMM);
  cudaFuncSetAttribute(gemm_kernel<1>, cudaFuncAttributeMaxDynamicSharedMemorySize, SM_GEMM);
  cudaFuncSetAttribute(recur_kernel, cudaFuncAttributeMaxDynamicSharedMemorySize, 16 * K_ * 4);

  prep_kernel<<<2548, 256>>>(latent, emb, target, out);

  long npX = (long)MPAD_ * KP_;        // 1,048,576
  long npW = (long)G4_ * KP_;          // 2,097,152
  long npF = (long)V_ * KP_;           // 16,384,000
  split_kernel<<<(unsigned)((npX + 255) / 256), 256>>>(Xp, AH, AL, npX);
  split_kernel<<<(unsigned)((npW + 255) / 256), 256>>>(W_ih, WH, WL, npW);
  split_kernel<<<(unsigned)((npF + 255) / 256), 256>>>(fc_w, FH, FL, npF);

  gemm_kernel<0><<<dim3(16, 32), 256, SM_GEMM>>>(AH, AL, WH, WL, b_ih, b_hh, nullptr);
  recur_kernel<<<128, 256, 16 * K_ * 4>>>(W_hh);
  split_kernel<<<(unsigned)((npX + 255) / 256), 256>>>(Hsp, AH, AL, npX);
  gemm_kernel<1><<<dim3(16, 250), 256, SM_GEMM>>>(AH, AL, FH, FL, fc_b, nullptr, out);
}

// round 13
// speedup vs baseline: 2.2386x; 1.0217x over previous
#include <cuda_runtime.h>
#include <cuda_bf16.h>
#include <math.h>

#define B_    16
#define L_    128
#define V_    32000
#define G4_   4096
#define K_    1024
#define KP_   512     // u32 bf16-pairs per row
#define T_    127
#define M_    2032
#define MPAD_ 2048
#define PD    20      // smem row stride in u32 (16 data + 4 pad), 16B aligned
#define NSLAB 32      // K_/32

__device__ float g_X[MPAD_ * K_];
__device__ float g_xall[(size_t)MPAD_ * G4_];
__device__ float g_Hs[MPAD_ * K_];
__device__ float g_h[B_ * K_];
__device__ unsigned g_bar;
// bf16 hi/lo split matrices (u32 = packed bf16x2 along K)
__device__ unsigned g_AH[MPAD_ * KP_], g_AL[MPAD_ * KP_];           // X or Hs
__device__ unsigned g_WH[G4_ * KP_],  g_WL[G4_ * KP_];              // W_ih
__device__ unsigned g_FH[(size_t)V_ * KP_], g_FL[(size_t)V_ * KP_]; // fc_w

// ---------------------------------------------------------------- prep
__global__ void __launch_bounds__(256) prep_kernel(
    const float* __restrict__ latent, const float* __restrict__ emb,
    const int* __restrict__ target, float* __restrict__ out) {
  long i = (long)blockIdx.x * blockDim.x + threadIdx.x;
  if (i == 0) g_bar = 0u;
  const long Z = (long)B_ * (V_ / 4);               // 128000: out l=0 rows
  const long X = (long)M_ * 256;                    // 520192
  if (i < Z) {
    long b = i / 8000, v4 = i % 8000;
    ((float4*)out)[b * ((long)L_ * V_ / 4) + v4] = make_float4(0.f, 0.f, 0.f, 0.f);
  } else if (i < Z + X) {
    long j = i - Z;
    int m = (int)(j / 256), c4 = (int)(j % 256);
    int s = m >> 4, b = m & 15;
    float4 v;
    if (c4 < 128) {
      int tok = target[b * L_ + s];
      v = ((const float4*)emb)[(size_t)tok * 128 + c4];
    } else {
      v = ((const float4*)latent)[b * 128 + (c4 - 128)];
    }
    ((float4*)g_X)[(size_t)m * 256 + c4] = v;
  } else {
    long k = i - Z - X;
    if (k < 4096) ((float4*)g_h)[k] = make_float4(0.f, 0.f, 0.f, 0.f);
  }
}

// ---------------------------------------------------------------- bf16 split
__device__ __forceinline__ unsigned pack2(__nv_bfloat16 a, __nv_bfloat16 b) {
  __nv_bfloat162 t; t.x = a; t.y = b;
  return *(unsigned*)&t;
}
__device__ __forceinline__ void bsplit2(float x0, float x1, unsigned& h, unsigned& l) {
  __nv_bfloat16 h0 = __float2bfloat16(x0);
  __nv_bfloat16 h1 = __float2bfloat16(x1);
  float r0 = x0 - __bfloat162float(h0);
  float r1 = x1 - __bfloat162float(h1);
  h = pack2(h0, h1);
  l = pack2(__float2bfloat16(r0), __float2bfloat16(r1));
}

__global__ void __launch_bounds__(256) split_kernel(
    const float* __restrict__ src, unsigned* __restrict__ hi,
    unsigned* __restrict__ lo, long npairs) {
  long i = (long)blockIdx.x * blockDim.x + threadIdx.x;
  if (i < npairs) {
    float2 v = ((const float2*)src)[i];
    unsigned h, l;
    bsplit2(v.x, v.y, h, l);
    hi[i] = h; lo[i] = l;
  }
}

// ---------------------------------------------------------------- GEMM helpers
__device__ __forceinline__ void mma16(float* c, const unsigned* a, const unsigned* b) {
  asm volatile(
    "mma.sync.aligned.m16n8k16.row.col.f32.bf16.bf16.f32 "
    "{%0,%1,%2,%3}, {%4,%5,%6,%7}, {%8,%9}, {%0,%1,%2,%3};\n"
    : "+f"(c[0]), "+f"(c[1]), "+f"(c[2]), "+f"(c[3])
    : "r"(a[0]), "r"(a[1]), "r"(a[2]), "r"(a[3]), "r"(b[0]), "r"(b[1]));
}
__device__ __forceinline__ void cpa16(unsigned saddr, const void* gptr) {
  asm volatile("cp.async.cg.shared.global [%0], [%1], 16;\n" :: "r"(saddr), "l"(gptr));
}
__device__ __forceinline__ void ldsm4(unsigned& r0, unsigned& r1, unsigned& r2,
                                      unsigned& r3, unsigned saddr) {
  asm volatile("ldmatrix.sync.aligned.m8n8.x4.shared.b16 {%0,%1,%2,%3}, [%4];\n"
               : "=r"(r0), "=r"(r1), "=r"(r2), "=r"(r3) : "r"(saddr));
}

#define TILE_U32 (128 * PD)

template <int EPI>
__global__ void __launch_bounds__(256, 2) gemm_kernel(
    const unsigned* __restrict__ AH, const unsigned* __restrict__ AL,
    const unsigned* __restrict__ BH, const unsigned* __restrict__ BL,
    const float* __restrict__ bias0, const float* __restrict__ bias1,
    float* __restrict__ Cout) {
  extern __shared__ unsigned smem[];   // [2 stages][4 tiles][128*PD]
  const int tid = threadIdx.x, lane = tid & 31, warp = tid >> 5;
  const int wm = warp >> 1, wn = warp & 1, grp = lane >> 2, tig = lane & 3;
  const int m0 = blockIdx.x * 128, n0 = blockIdx.y * 128;

  const unsigned sbase = (unsigned)__cvta_generic_to_shared(smem);
  const int row = tid >> 2, c4 = (tid & 3) * 4;   // cp.async coords

  // ldmatrix lane-offset precompute (u32 index within a tile)
  const int g8 = lane & 7, q = lane >> 3;
  // A(mi): reg q -> rows (m16 base)+((q&1)*8)+g8, colpair +((q>>1)*4)
  int offA[2];
#pragma unroll
  for (int mi = 0; mi < 2; mi++)
    offA[mi] = (wm * 32 + mi * 16 + ((q & 1) << 3) + g8) * PD + ((q >> 1) << 2);
  // B(j: ni pair): reg q -> rows (n16 base)+((q>>1)*8)+g8, colpair +((q&1)*4)
  int offB[4];
#pragma unroll
  for (int j = 0; j < 4; j++)
    offB[j] = (wn * 64 + j * 16 + ((q >> 1) << 3) + g8) * PD + ((q & 1) << 2);

  float acc[2][8][4];
#pragma unroll
  for (int a = 0; a < 2; a++)
#pragma unroll
    for (int b = 0; b < 8; b++)
#pragma unroll
      for (int c = 0; c < 4; c++) acc[a][b][c] = 0.f;

  const unsigned* gsrc[4] = {AH, AL, BH, BL};

  auto issue = [&](int st, int kp0) {
#pragma unroll
    for (int t = 0; t < 4; t++) {
      const unsigned* g = gsrc[t];
      int rbase = (t < 2) ? m0 : n0;
      unsigned sdst = sbase + ((st * 4 + t) * TILE_U32) * 4u;
#pragma unroll
      for (int j = 0; j < 2; j++) {
        int r = row + j * 64;
        cpa16(sdst + (r * PD + c4) * 4u,
              g + (size_t)(rbase + r) * KP_ + kp0 + c4);
      }
    }
    asm volatile("cp.async.commit_group;\n");
  };

  issue(0, 0);

  for (int s = 0; s < NSLAB; s++) {
    const int st = s & 1;
    if (s + 1 < NSLAB) {
      issue(st ^ 1, (s + 1) * 16);
      asm volatile("cp.async.wait_group 1;\n");
    } else {
      asm volatile("cp.async.wait_group 0;\n");
    }
    __syncthreads();

    const unsigned ahB = sbase + ((st * 4 + 0) * TILE_U32) * 4u;
    const unsigned alB = sbase + ((st * 4 + 1) * TILE_U32) * 4u;
    const unsigned bhB = sbase + ((st * 4 + 2) * TILE_U32) * 4u;
    const unsigned blB = sbase + ((st * 4 + 3) * TILE_U32) * 4u;

#pragma unroll
    for (int kk = 0; kk < 2; kk++) {
      const int pb4 = kk * 8 * 4;     // byte offset of pair base
      unsigned aH[2][4], aL[2][4];
#pragma unroll
      for (int mi = 0; mi < 2; mi++) {
        ldsm4(aH[mi][0], aH[mi][1], aH[mi][2], aH[mi][3], ahB + offA[mi] * 4u + pb4);
        ldsm4(aL[mi][0], aL[mi][1], aL[mi][2], aL[mi][3], alB + offA[mi] * 4u + pb4);
      }
#pragma unroll
      for (int j = 0; j < 4; j++) {
        unsigned bH[4], bL[4];
        ldsm4(bH[0], bH[1], bH[2], bH[3], bhB + offB[j] * 4u + pb4);
        ldsm4(bL[0], bL[1], bL[2], bL[3], blB + offB[j] * 4u + pb4);
#pragma unroll
        for (int mi = 0; mi < 2; mi++) {
          mma16(acc[mi][2 * j],     aH[mi], bH);
          mma16(acc[mi][2 * j],     aH[mi], bL);
          mma16(acc[mi][2 * j],     aL[mi], bH);
          mma16(acc[mi][2 * j + 1], aH[mi], bH + 2);
          mma16(acc[mi][2 * j + 1], aH[mi], bL + 2);
          mma16(acc[mi][2 * j + 1], aL[mi], bH + 2);
        }
      }
    }
    __syncthreads();
  }

#pragma unroll
  for (int mi = 0; mi < 2; mi++)
#pragma unroll
    for (int ni = 0; ni < 8; ni++) {
      int mr = m0 + wm * 32 + mi * 16 + grp;
      int nc = n0 + wn * 64 + ni * 8 + tig * 2;
      float* cp = acc[mi][ni];
      float b0 = bias0[nc] + ((EPI == 0) ? bias1[nc] : 0.f);
      float b1 = bias0[nc + 1] + ((EPI == 0) ? bias1[nc + 1] : 0.f);
      if (EPI == 0) {
        if (mr < M_) {
          g_xall[(size_t)mr * G4_ + nc] = cp[0] + b0;
          g_xall[(size_t)mr * G4_ + nc + 1] = cp[1] + b1;
        }
        if (mr + 8 < M_) {
          g_xall[(size_t)(mr + 8) * G4_ + nc] = cp[2] + b0;
          g_xall[(size_t)(mr + 8) * G4_ + nc + 1] = cp[3] + b1;
        }
      } else {
        if (mr < M_) {
          size_t o = ((size_t)(mr & 15) * L_ + (mr >> 4) + 1) * V_ + nc;
          Cout[o] = cp[0] + b0; Cout[o + 1] = cp[1] + b1;
        }
        if (mr + 8 < M_) {
          int m2 = mr + 8;
          size_t o = ((size_t)(m2 & 15) * L_ + (m2 >> 4) + 1) * V_ + nc;
          Cout[o] = cp[2] + b0; Cout[o + 1] = cp[3] + b1;
        }
      }
    }
}

// ---------------------------------------------------------------- recurrence
__device__ __forceinline__ float sigf(float x) { return 1.f / (1.f + __expf(-x)); }

__global__ void __launch_bounds__(256) recur_kernel(const float* __restrict__ Whh) {
  extern __shared__ float hs[];   // 16 x 1024 floats
  const int tid = threadIdx.x, lane = tid & 31, warp = tid >> 5;
  const int u = blockIdx.x * 8 + warp;   // hidden unit owned by this warp
  float c = 0.f;
  unsigned tgt = 0;

  for (int s = 0; s < T_; s++) {
    for (int j = tid; j < 4096; j += 256)
      ((float4*)hs)[j] = __ldcg((const float4*)g_h + j);
    __syncthreads();

    float acc[4][16];
#pragma unroll
    for (int g = 0; g < 4; g++)
#pragma unroll
      for (int b = 0; b < 16; b++) acc[g][b] = 0.f;

#pragma unroll
    for (int i = 0; i < 8; i++) {
      const int k = lane * 4 + i * 128;
      float4 w0 = *(const float4*)(Whh + ((size_t)(0 * K_ + u)) * K_ + k);
      float4 w1 = *(const float4*)(Whh + ((size_t)(1 * K_ + u)) * K_ + k);
      float4 w2 = *(const float4*)(Whh + ((size_t)(2 * K_ + u)) * K_ + k);
      float4 w3 = *(const float4*)(Whh + ((size_t)(3 * K_ + u)) * K_ + k);
#pragma unroll
      for (int b = 0; b < 16; b++) {
        float4 h4 = *(const float4*)(hs + b * K_ + k);
        acc[0][b] += w0.x * h4.x; acc[0][b] += w0.y * h4.y;
        acc[0][b] += w0.z * h4.z; acc[0][b] += w0.w * h4.w;
        acc[1][b] += w1.x * h4.x; acc[1][b] += w1.y * h4.y;
        acc[1][b] += w1.z * h4.z; acc[1][b] += w1.w * h4.w;
        acc[2][b] += w2.x * h4.x; acc[2][b] += w2.y * h4.y;
        acc[2][b] += w2.z * h4.z; acc[2][b] += w2.w * h4.w;
        acc[3][b] += w3.x * h4.x; acc[3][b] += w3.y * h4.y;
        acc[3][b] += w3.z * h4.z; acc[3][b] += w3.w * h4.w;
      }
    }

#pragma unroll
    for (int g = 0; g < 4; g++)
#pragma unroll
      for (int b = 0; b < 16; b++)
#pragma unroll
        for (int off = 16; off; off >>= 1)
          acc[g][b] += __shfl_xor_sync(0xffffffffu, acc[g][b], off);

    if (lane < 16) {
      float gi = 0.f, gf = 0.f, gg = 0.f, go = 0.f;
#pragma unroll
      for (int b = 0; b < 16; b++)
        if (b == lane) { gi = acc[0][b]; gf = acc[1][b]; gg = acc[2][b]; go = acc[3][b]; }
      size_t xr = ((size_t)s * 16 + lane) * G4_ + u;
      gi += g_xall[xr];
      gf += g_xall[xr + 1024];
      gg += g_xall[xr + 2048];
      go += g_xall[xr + 3072];
      c = sigf(gf) * c + sigf(gi) * tanhf(gg);
      float h = sigf(go) * tanhf(c);
      g_h[lane * K_ + u] = h;
      g_Hs[((size_t)s * 16 + lane) * K_ + u] = h;
    }

    __threadfence();
    __syncthreads();
    tgt += gridDim.x;
    if (tid == 0) {
      atomicAdd(&g_bar, 1u);
      while (*(volatile unsigned*)&g_bar < tgt) {}
    }
    __syncthreads();
  }
}

// ---------------------------------------------------------------- launch
extern "C" void kernel_launch(void* const* d_in, const int* in_sizes, int n_in,
                              void* d_out, int out_size) {
  const float* latent = (const float*)d_in[0];
  const float* emb    = (const float*)d_in[1];
  const float* W_ih   = (const float*)d_in[2];
  const float* W_hh   = (const float*)d_in[3];
  const float* b_ih   = (const float*)d_in[4];
  const float* b_hh   = (const float*)d_in[5];
  const float* fc_w   = (const float*)d_in[6];
  const float* fc_b   = (const float*)d_in[7];
  const int*   target = (const int*)d_in[8];
  float* out = (float*)d_out;

  unsigned *AH, *AL, *WH, *WL, *FH, *FL;
  float *Xp, *Hsp;
  cudaGetSymbolAddress((void**)&AH, g_AH);
  cudaGetSymbolAddress((void**)&AL, g_AL);
  cudaGetSymbolAddress((void**)&WH, g_WH);
  cudaGetSymbolAddress((void**)&WL, g_WL);
  cudaGetSymbolAddress((void**)&FH, g_FH);
  cudaGetSymbolAddress((void**)&FL, g_FL);
  cudaGetSymbolAddress((void**)&Xp, g_X);
  cudaGetSymbolAddress((void**)&Hsp, g_Hs);

  const int SM_GEMM = 2 * 4 * TILE_U32 * 4;   // 81920 B
  cudaFuncSetAttribute(gemm_kernel<0>, cudaFuncAttributeMaxDynamicSharedMemorySize, SM_GEMM);
  cudaFuncSetAttribute(gemm_kernel<1>, cudaFuncAttributeMaxDynamicSharedMemorySize, SM_GEMM);
  cudaFuncSetAttribute(recur_kernel, cudaFuncAttributeMaxDynamicSharedMemorySize, 16 * K_ * 4);

  prep_kernel<<<2548, 256>>>(latent, emb, target, out);

  long npX = (long)MPAD_ * KP_;        // 1,048,576
  long npW = (long)G4_ * KP_;          // 2,097,152
  long npF = (long)V_ * KP_;           // 16,384,000
  split_kernel<<<(unsigned)((npX + 255) / 256), 256>>>(Xp, AH, AL, npX);
  split_kernel<<<(unsigned)((npW + 255) / 256), 256>>>(W_ih, WH, WL, npW);
  split_kernel<<<(unsigned)((npF + 255) / 256), 256>>>(fc_w, FH, FL, npF);

  gemm_kernel<0><<<dim3(16, 32), 256, SM_GEMM>>>(AH, AL, WH, WL, b_ih, b_hh, nullptr);
  recur_kernel<<<128, 256, 16 * K_ * 4>>>(W_hh);
  split_kernel<<<(unsigned)((npX + 255) / 256), 256>>>(Hsp, AH, AL, npX);
  gemm_kernel<1><<<dim3(16, 250), 256, SM_GEMM>>>(AH, AL, FH, FL, fc_b, nullptr, out);
}